// round 16
// baseline (speedup 1.0000x reference)
#include <cuda_runtime.h>
#include <cuda_bf16.h>
#include <cstdint>

// ---------------------------------------------------------------------------
// helpers
// ---------------------------------------------------------------------------
__device__ __forceinline__ uint32_t pkbf(float lo, float hi) {
    uint32_t r; asm("cvt.rn.bf16x2.f32 %0,%1,%2;" : "=r"(r) : "f"(hi), "f"(lo));
    return r;
}
__device__ __forceinline__ void mma16(float* c, uint32_t a0, uint32_t a1,
                                      uint32_t a2, uint32_t a3,
                                      uint32_t b0, uint32_t b1) {
    asm("mma.sync.aligned.m16n8k16.row.col.f32.bf16.bf16.f32 "
        "{%0,%1,%2,%3},{%4,%5,%6,%7},{%8,%9},{%0,%1,%2,%3};"
        : "+f"(c[0]), "+f"(c[1]), "+f"(c[2]), "+f"(c[3])
        : "r"(a0), "r"(a1), "r"(a2), "r"(a3), "r"(b0), "r"(b1));
}
__device__ __forceinline__ void ldsm4(uint32_t* a, uint32_t saddr) {
    asm volatile("ldmatrix.sync.aligned.m8n8.x4.shared.b16 {%0,%1,%2,%3},[%4];"
                 : "=r"(a[0]), "=r"(a[1]), "=r"(a[2]), "=r"(a[3]) : "r"(saddr));
}
__device__ __forceinline__ uint32_t vmax2(uint32_t a, uint32_t b) {
    uint32_t r; asm("max.bf16x2 %0,%1,%2;" : "=r"(r) : "r"(a), "r"(b)); return r;
}
__device__ __forceinline__ uint32_t vmin2(uint32_t a, uint32_t b) {
    uint32_t r; asm("min.bf16x2 %0,%1,%2;" : "=r"(r) : "r"(a), "r"(b)); return r;
}
__device__ __forceinline__ uint32_t vfma2(uint32_t a, uint32_t b, uint32_t c) {
    uint32_t r; asm("fma.rn.bf16x2 %0,%1,%2,%3;" : "=r"(r) : "r"(a), "r"(b), "r"(c));
    return r;
}

// ---------------------------------------------------------------------------
// Scratch
// ---------------------------------------------------------------------------
__device__ __nv_bfloat16 g_s1[1024 * 32 * 32 * 36];  // conv1 out, NHWC bf16
__device__ __nv_bfloat16 g_s2[1024 * 16 * 16 * 36];  // conv2 out, NHWC bf16
__device__ __nv_bfloat16 g_s3[1024 * 8 * 8 * 36];    // conv3 out, NHWC bf16
__device__ float         g_h [1024 * 12];
__device__ __nv_bfloat16 g_p1[1024 * 32 * 32 * 12];  // private conv, NHWC bf16
__device__ float         g_pf[1024 * 12];
__device__ float         g_pw[12 * 12288];           // Pl_W[dom] permuted (NHWC K)
__device__ float         g_fw[12 * 2304];            // Ws_fc_W permuted (NHWC K)
__device__ uint32_t      g_bf1[960];                 // packed first-conv B (shared)
__device__ uint32_t      g_bfp[960];                 // packed first-conv B (private)
__device__ uint32_t      g_bmid[7680];               // packed mid-conv B

// ---------------------------------------------------------------------------
// One-time prep: pack conv weights into SMEM images; permute FC weights.
// ---------------------------------------------------------------------------
__global__ void prep_k(const float* __restrict__ Ws_in_W,
                       const float* __restrict__ Pc_W,
                       const int*   __restrict__ dom,
                       const float* __restrict__ Ws_hid_W,
                       const float* __restrict__ Pl_W,
                       const float* __restrict__ Ws_fc_W,
                       float* __restrict__ pw,
                       float* __restrict__ fw,
                       uint32_t* __restrict__ bf1,
                       uint32_t* __restrict__ bfp,
                       uint32_t* __restrict__ bmid) {
    int d = *dom;
    const float* Wp = Pc_W + d * 12 * 27;
    const float* Wl = Pl_W + (size_t)d * 147456;
    const int TOT = 960 + 960 + 7680 + 147456 + 27648;
    for (int i = blockIdx.x * 256 + threadIdx.x; i < TOT; i += gridDim.x * 256) {
        if (i < 960) {                                  // first conv, shared (36 oc)
            int ky = i / 320, rem = i % 320, j = rem / 40, oc = rem % 40;
            int kx = j >> 1, ch0 = (j & 1) * 2;
            float w0 = 0.f, w1 = 0.f;
            if (oc < 36 && kx < 3) {
                w0 = Ws_in_W[oc * 27 + ch0 * 9 + ky * 3 + kx];
                if (ch0 + 1 < 3) w1 = Ws_in_W[oc * 27 + (ch0 + 1) * 9 + ky * 3 + kx];
            }
            bf1[i] = pkbf(w0, w1);
        } else if (i < 1920) {                          // first conv, private (12 oc)
            int ii = i - 960;
            int ky = ii / 320, rem = ii % 320, j = rem / 40, oc = rem % 40;
            int kx = j >> 1, ch0 = (j & 1) * 2;
            float w0 = 0.f, w1 = 0.f;
            if (oc < 12 && kx < 3) {
                w0 = Wp[oc * 27 + ch0 * 9 + ky * 3 + kx];
                if (ch0 + 1 < 3) w1 = Wp[oc * 27 + (ch0 + 1) * 9 + ky * 3 + kx];
            }
            bfp[ii] = pkbf(w0, w1);
        } else if (i < 9600) {                          // mid conv B image
            int ii = i - 1920;
            int ky = ii / 2560, rem = ii - ky * 2560;
            int j = rem / 40, oc = rem % 40;
            int p = j / 20, jj = j - 20 * p;
            float w0 = 0.f, w1 = 0.f;
            if (p < 3 && jj < 18 && oc < 36) {
                w0 = Ws_hid_W[oc * 324 + (2 * jj) * 9 + ky * 3 + p];
                w1 = Ws_hid_W[oc * 324 + (2 * jj + 1) * 9 + ky * 3 + p];
            }
            bmid[ii] = pkbf(w0, w1);
        } else if (i < 9600 + 147456) {                 // Pl_W permute to NHWC-K
            int ii = i - 9600;
            int o = ii / 12288, rr = ii - o * 12288;
            int p = rr / 12, c = rr - 12 * p;
            pw[ii] = Wl[o * 12288 + c * 1024 + p];
        } else {                                        // Ws_fc_W permute to NHWC-K
            int ii = i - 9600 - 147456;
            int o = ii / 2304, rr = ii - o * 2304;
            int p = rr / 36, c = rr - 36 * p;
            fw[ii] = Ws_fc_W[o * 2304 + c * 64 + p];
        }
    }
}

// ---------------------------------------------------------------------------
// Packed epilogue: bias in f32, pack bf16x2, pool via 4 shfl + max.bf16x2,
// act in bf16x2, store NHWC u32 pairs.
// ---------------------------------------------------------------------------
template <int OCR, int PO, bool LEAKY>
__device__ __forceinline__ void epi_pk(const float acc[][4], int NF,
                                       int ty, int tx, int g, int t,
                                       const float* b_s, uint32_t* o32) {
    const uint32_t C001 = 0x3A833A83u;   // bf16x2(0.001, 0.001)
    for (int nf = 0; nf < NF; nf++) {
        int oc = nf * 8 + 2 * t;
        float b0 = b_s[oc], b1 = b_s[oc + 1];
        uint32_t p01 = pkbf(acc[nf][0] + b0, acc[nf][1] + b1);
        uint32_t p23 = pkbf(acc[nf][2] + b0, acc[nf][3] + b1);
        p01 = vmax2(p01, __shfl_xor_sync(0xffffffffu, p01, 4));
        p23 = vmax2(p23, __shfl_xor_sync(0xffffffffu, p23, 4));
        p01 = vmax2(p01, __shfl_xor_sync(0xffffffffu, p01, 16));
        p23 = vmax2(p23, __shfl_xor_sync(0xffffffffu, p23, 16));
        if (LEAKY) {
            p01 = vfma2(vmin2(p01, 0u), C001, vmax2(p01, 0u));
            p23 = vfma2(vmin2(p23, 0u), C001, vmax2(p23, 0u));
        } else {
            p01 = vmax2(p01, 0u);
            p23 = vmax2(p23, 0u);
        }
        if (((g & 1) == 0) && (g < 4) && oc < OCR) {
            int px  = tx * 2 + (g >> 1);
            int py0 = ty * 2;
            o32[( py0      * PO + px) * (OCR / 2) + (oc >> 1)] = p01;
            o32[((py0 + 1) * PO + px) * (OCR / 2) + (oc >> 1)] = p23;
        }
    }
}

// ---------------------------------------------------------------------------
// First-conv body: Cin=3 (4ch-padded NHWC bf16), H=64, conv+bias+act+pool.
// ---------------------------------------------------------------------------
template <int OCR, int OCP, bool LEAKY, bool USE_DOM>
__device__ void conv_first_body(int b, const float* __restrict__ x,
                                const uint32_t* __restrict__ pb,
                                const float* __restrict__ bias,
                                const int* __restrict__ dom,
                                uint32_t* __restrict__ outb) {
    constexpr int P32 = 144;
    constexpr int NF  = OCP / 8;
    constexpr int SB  = 40;
    extern __shared__ uint32_t sm32[];
    uint32_t* in32 = sm32;                     // 66*144
    uint32_t* B32  = sm32 + 66 * P32;          // 960
    float*    b_s  = (float*)(B32 + 960);

    int tid = threadIdx.x;
    if (USE_DOM) { int d = *dom; bias += d * OCR; }

    {
        uint4* B4 = (uint4*)B32;
        const uint4* pb4 = (const uint4*)pb;
        for (int i = tid; i < 240; i += 256) B4[i] = pb4[i];
    }
    for (int i = tid; i < 2 * P32; i += 256)
        in32[(i < P32 ? 0 : 65) * P32 + (i % P32)] = 0u;
    for (int i = tid; i < 64 * 16; i += 256) {
        int rr = i / 16 + 1, cc = i % 16;
        in32[rr * P32 + (cc < 2 ? cc : 128 + cc)] = 0u;
    }
    const float* src = x + (size_t)b * 3 * 4096;
    for (int p = tid; p < 4096; p += 256) {
        int y = p >> 6, xx = p & 63;
        int dst = (y + 1) * P32 + (xx + 1) * 2;
        in32[dst]     = pkbf(src[p], src[4096 + p]);
        in32[dst + 1] = pkbf(src[8192 + p], 0.f);
    }
    if (tid < OCP) b_s[tid] = (tid < OCR) ? bias[tid] : 0.f;
    __syncthreads();

    int lane = tid & 31, warp = tid >> 5;
    int g = lane >> 2, t = lane & 3;
    int dy = g >> 2, dxl = g & 3;
    uint32_t* outp = outb + (size_t)b * 32 * 32 * (OCR / 2);

    for (int s = warp; s < 128; s += 8) {
        int ty = s >> 3, tx0 = (2 * s) & 15;
        const uint32_t* ab = in32 + (ty * 4 + dy) * P32 + (tx0 * 4 + dxl) * 2 + t;
        float acc[2][NF][4];
        #pragma unroll
        for (int j = 0; j < 2; j++)
            #pragma unroll
            for (int nf = 0; nf < NF; nf++)
                #pragma unroll
                for (int q = 0; q < 4; q++) acc[j][nf][q] = 0.f;

        #pragma unroll
        for (int ky = 0; ky < 3; ky++) {
            const uint32_t* ap = ab + ky * P32;
            uint32_t a00 = ap[0], a01 = ap[2 * P32],     a02 = ap[4],  a03 = ap[2 * P32 + 4];
            uint32_t a10 = ap[8], a11 = ap[2 * P32 + 8], a12 = ap[12], a13 = ap[2 * P32 + 12];
            const uint32_t* bp = B32 + ky * 8 * SB + t * SB + g;
            #pragma unroll
            for (int nf = 0; nf < NF; nf++) {
                uint32_t b0 = bp[nf * 8], b1 = bp[4 * SB + nf * 8];
                mma16(acc[0][nf], a00, a01, a02, a03, b0, b1);
                mma16(acc[1][nf], a10, a11, a12, a13, b0, b1);
            }
        }
        epi_pk<OCR, 32, LEAKY>(acc[0], NF, ty, tx0,     g, t, b_s, outp);
        epi_pk<OCR, 32, LEAKY>(acc[1], NF, ty, tx0 + 1, g, t, b_s, outp);
    }
}

__global__ __launch_bounds__(256) void conv_first_fused(
        const float* __restrict__ x_s, const uint32_t* __restrict__ bf1,
        const float* __restrict__ Wsb,
        const float* __restrict__ x_p, const uint32_t* __restrict__ bfp,
        const float* __restrict__ Pcb, const int* __restrict__ dom,
        uint32_t* __restrict__ s1, uint32_t* __restrict__ p1) {
    if (blockIdx.x < 1024)
        conv_first_body<36, 40, false, false>(blockIdx.x, x_s, bf1, Wsb, nullptr, s1);
    else
        conv_first_body<12, 16, true, true>(blockIdx.x - 1024, x_p, bfp, Pcb, dom, p1);
}

// ---------------------------------------------------------------------------
// Mid conv 32->16: 2 half-image CTAs per image (18-row window). NHWC bf16 out.
// ---------------------------------------------------------------------------
__global__ __launch_bounds__(256) void conv_mid32_k(const __nv_bfloat16* __restrict__ in,
                                                    const float* __restrict__ bias,
                                                    const uint32_t* __restrict__ bmid,
                                                    uint32_t* __restrict__ outb) {
    constexpr int P32 = 688, RL = 18;
    extern __shared__ uint32_t sm32[];
    uint32_t* in32 = sm32;                     // 18*688
    uint32_t* B32  = sm32 + RL * P32;          // 7680
    float*    b_s  = (float*)(B32 + 7680);

    int b = blockIdx.x >> 1, h = blockIdx.x & 1, tid = threadIdx.x;
    {
        uint4* B4 = (uint4*)B32;
        const uint4* pb4 = (const uint4*)bmid;
        for (int i = tid; i < 1920; i += 256) B4[i] = pb4[i];
    }
    int lr_bad = h ? 17 : 0;
    for (int i = tid; i < P32; i += 256) in32[lr_bad * P32 + i] = 0u;
    for (int i = tid; i < RL * 48; i += 256) {
        int lr = i / 48, cc = i % 48;
        in32[lr * P32 + (cc < 20 ? cc : 660 + (cc - 20))] = 0u;
    }
    const uint2* src2 = (const uint2*)(in + (size_t)b * 32 * 32 * 36);
    uint2* dst2 = (uint2*)in32;
    for (int i = tid; i < 17 * 32 * 10; i += 256) {
        int lrv = i / 320, rem = i - lrv * 320;
        int xx = rem / 10, q = rem - xx * 10;
        int lr = lrv + (h ? 0 : 1);
        int gy = h * 16 - 1 + lr;
        uint2 v = (q < 9) ? src2[(gy * 32 + xx) * 9 + q] : make_uint2(0u, 0u);
        dst2[((lr * P32 + (xx + 1) * 20) >> 1) + q] = v;
    }
    if (tid < 40) b_s[tid] = (tid < 36) ? bias[tid] : 0.f;
    __syncthreads();

    int lane = tid & 31, warp = tid >> 5;
    int g = lane >> 2, t = lane & 3;
    int r = lane & 15, kh = lane >> 4;
    int rowz = ((r & 7) >> 2) + 2 * (r >> 3);
    int colp = r & 3;
    uint32_t sbase = (uint32_t)__cvta_generic_to_shared(in32);
    uint32_t* outp = outb + (size_t)b * 16 * 16 * 18;

    for (int s = warp; s < 16; s += 8) {
        int ty_l = (2 * s) / 8, tx0 = (2 * s) % 8;
        uint32_t abase = sbase + ((ty_l * 4 + rowz) * P32 + (tx0 * 4 + colp) * 20 + kh * 4) * 4;
        float acc[2][5][4];
        #pragma unroll
        for (int j = 0; j < 2; j++)
            #pragma unroll
            for (int nf = 0; nf < 5; nf++)
                #pragma unroll
                for (int q = 0; q < 4; q++) acc[j][nf][q] = 0.f;

        #pragma unroll
        for (int ky = 0; ky < 3; ky++) {
            uint32_t kbase = abase + ky * (P32 * 4);
            #pragma unroll
            for (int f = 0; f < 8; f++) {
                uint32_t A0[4], A1[4];
                ldsm4(A0, kbase + f * 32);
                ldsm4(A1, kbase + f * 32 + 320);
                const uint32_t* bp = B32 + ky * 2560 + (f * 8 + t) * 40 + g;
                #pragma unroll
                for (int nf = 0; nf < 5; nf++) {
                    uint32_t b0 = bp[nf * 8], b1 = bp[160 + nf * 8];
                    mma16(acc[0][nf], A0[0], A0[1], A0[2], A0[3], b0, b1);
                    mma16(acc[1][nf], A1[0], A1[1], A1[2], A1[3], b0, b1);
                }
            }
        }
        epi_pk<36, 16, false>(acc[0], 5, ty_l + h * 4, tx0,     g, t, b_s, outp);
        epi_pk<36, 16, false>(acc[1], 5, ty_l + h * 4, tx0 + 1, g, t, b_s, outp);
    }
}

// ---------------------------------------------------------------------------
// Mid conv 16->8: 2 images per block (512 blocks, ~3.5 CTA/SM). NHWC bf16 out.
// ---------------------------------------------------------------------------
__global__ __launch_bounds__(256) void conv_mid16_k(const __nv_bfloat16* __restrict__ in,
                                                    const float* __restrict__ bias,
                                                    const uint32_t* __restrict__ bmid,
                                                    uint32_t* __restrict__ outb) {
    constexpr int P32 = 368, ROWS = 18, HH = 16;
    extern __shared__ uint32_t sm32[];
    uint32_t* in32 = sm32;                     // 18*368
    uint32_t* B32  = sm32 + ROWS * P32;        // 7680
    float*    b_s  = (float*)(B32 + 7680);

    int tid = threadIdx.x;
    {
        uint4* B4 = (uint4*)B32;
        const uint4* pb4 = (const uint4*)bmid;
        for (int i = tid; i < 1920; i += 256) B4[i] = pb4[i];
    }
    for (int i = tid; i < 2 * P32; i += 256)
        in32[(i < P32 ? 0 : ROWS - 1) * P32 + (i % P32)] = 0u;
    for (int i = tid; i < HH * 48; i += 256) {
        int rr = i / 48 + 1, cc = i % 48;
        in32[rr * P32 + (cc < 20 ? cc : (HH + 1) * 20 + (cc - 20))] = 0u;
    }
    if (tid < 40) b_s[tid] = (tid < 36) ? bias[tid] : 0.f;

    int lane = tid & 31, warp = tid >> 5;
    int g = lane >> 2, t = lane & 3;
    int r = lane & 15, kh = lane >> 4;
    int rowz = ((r & 7) >> 2) + 2 * (r >> 3);
    int colp = r & 3;
    uint32_t sbase = (uint32_t)__cvta_generic_to_shared(in32);

    for (int im = 0; im < 2; im++) {
        int b = blockIdx.x * 2 + im;
        __syncthreads();                       // smem safe to overwrite / ready
        const uint2* src2 = (const uint2*)(in + (size_t)b * HH * HH * 36);
        uint2* dst2 = (uint2*)in32;
        for (int i = tid; i < HH * HH * 10; i += 256) {
            int p = i / 10, q = i - p * 10;
            int y = p / HH, xx = p % HH;
            uint2 v = (q < 9) ? src2[p * 9 + q] : make_uint2(0u, 0u);
            dst2[(((y + 1) * P32 + (xx + 1) * 20) >> 1) + q] = v;
        }
        __syncthreads();

        uint32_t* outp = outb + (size_t)b * 8 * 8 * 18;
        int s = warp;                          // 8 steps, 1 per warp
        int ty = (2 * s) / 4, tx0 = (2 * s) % 4;
        uint32_t abase = sbase + ((ty * 4 + rowz) * P32 + (tx0 * 4 + colp) * 20 + kh * 4) * 4;
        float acc[2][5][4];
        #pragma unroll
        for (int j = 0; j < 2; j++)
            #pragma unroll
            for (int nf = 0; nf < 5; nf++)
                #pragma unroll
                for (int q = 0; q < 4; q++) acc[j][nf][q] = 0.f;

        #pragma unroll
        for (int ky = 0; ky < 3; ky++) {
            uint32_t kbase = abase + ky * (P32 * 4);
            #pragma unroll
            for (int f = 0; f < 8; f++) {
                uint32_t A0[4], A1[4];
                ldsm4(A0, kbase + f * 32);
                ldsm4(A1, kbase + f * 32 + 320);
                const uint32_t* bp = B32 + ky * 2560 + (f * 8 + t) * 40 + g;
                #pragma unroll
                for (int nf = 0; nf < 5; nf++) {
                    uint32_t b0 = bp[nf * 8], b1 = bp[160 + nf * 8];
                    mma16(acc[0][nf], A0[0], A0[1], A0[2], A0[3], b0, b1);
                    mma16(acc[1][nf], A1[0], A1[1], A1[2], A1[3], b0, b1);
                }
            }
        }
        epi_pk<36, 8, false>(acc[0], 5, ty, tx0,     g, t, b_s, outp);
        epi_pk<36, 8, false>(acc[1], 5, ty, tx0 + 1, g, t, b_s, outp);
    }
}

// ---------------------------------------------------------------------------
// Fused FCs, SMEM-staged weights, 16 samples/block (16 threads per sample).
// blocks [0,64): shared fc (bf16 in, K=2304, relu) -> g_h
// blocks [64,128): private fc (bf16 in, K=12288, chunks of 2048) -> g_pf
// ---------------------------------------------------------------------------
__device__ void fc_shared_body(int b, const __nv_bfloat16* __restrict__ in,
                               const float* __restrict__ fw,
                               const float* __restrict__ bias,
                               float* __restrict__ out) {
    extern __shared__ float ws[];              // 12*2304
    int tid = threadIdx.x, lane = tid & 31, l16 = lane & 15;
    int s = (tid >> 5) * 2 + (lane >> 4);      // 0..15
    for (int i = tid; i < 12 * 2304; i += 256) ws[i] = fw[i];
    __syncthreads();
    int smp = b * 16 + s;
    const uint2* x2 = (const uint2*)(in + (size_t)smp * 2304);
    float acc[12];
    #pragma unroll
    for (int o = 0; o < 12; o++) acc[o] = 0.f;
    #pragma unroll 2
    for (int i = 0; i < 36; i++) {
        int k4 = l16 + i * 16;
        uint2 xa = x2[k4];
        float2 x01 = __bfloat1622float2(*(const __nv_bfloat162*)&xa.x);
        float2 x23 = __bfloat1622float2(*(const __nv_bfloat162*)&xa.y);
        #pragma unroll
        for (int o = 0; o < 12; o++) {
            float4 wa = ((const float4*)(ws + o * 2304))[k4];
            acc[o] = fmaf(x01.x, wa.x, fmaf(x01.y, wa.y,
                      fmaf(x23.x, wa.z, fmaf(x23.y, wa.w, acc[o]))));
        }
    }
    #pragma unroll
    for (int o = 0; o < 12; o++)
        #pragma unroll
        for (int off = 8; off; off >>= 1)
            acc[o] += __shfl_down_sync(0xffffffffu, acc[o], off, 16);
    if (l16 == 0)
        #pragma unroll
        for (int o = 0; o < 12; o++)
            out[smp * 12 + o] = fmaxf(acc[o] + bias[o], 0.f);
}

__device__ void fc_priv_body(int b, const __nv_bfloat16* __restrict__ in,
                             const float* __restrict__ pw,
                             const float* __restrict__ bias,
                             const int* __restrict__ dom,
                             float* __restrict__ out) {
    extern __shared__ float ws[];              // 12*2048 per chunk
    int d = *dom;
    int tid = threadIdx.x, lane = tid & 31, l16 = lane & 15;
    int s = (tid >> 5) * 2 + (lane >> 4);
    int smp = b * 16 + s;
    const __nv_bfloat16* xp = in + (size_t)smp * 12288;
    float acc[12];
    #pragma unroll
    for (int o = 0; o < 12; o++) acc[o] = 0.f;

    for (int kc0 = 0; kc0 < 12288; kc0 += 2048) {
        __syncthreads();
        for (int i = tid; i < 12 * 2048; i += 256)
            ws[i] = pw[(size_t)(i >> 11) * 12288 + kc0 + (i & 2047)];
        __syncthreads();
        const uint2* x2 = (const uint2*)(xp + kc0);
        #pragma unroll 2
        for (int i = 0; i < 32; i++) {
            int k4 = l16 + i * 16;
            uint2 xa = x2[k4];
            float2 x01 = __bfloat1622float2(*(const __nv_bfloat162*)&xa.x);
            float2 x23 = __bfloat1622float2(*(const __nv_bfloat162*)&xa.y);
            #pragma unroll
            for (int o = 0; o < 12; o++) {
                float4 wa = ((const float4*)(ws + o * 2048))[k4];
                acc[o] = fmaf(x01.x, wa.x, fmaf(x01.y, wa.y,
                          fmaf(x23.x, wa.z, fmaf(x23.y, wa.w, acc[o]))));
            }
        }
    }
    #pragma unroll
    for (int o = 0; o < 12; o++)
        #pragma unroll
        for (int off = 8; off; off >>= 1)
            acc[o] += __shfl_down_sync(0xffffffffu, acc[o], off, 16);
    if (l16 == 0)
        #pragma unroll
        for (int o = 0; o < 12; o++)
            out[smp * 12 + o] = acc[o] + bias[d * 12 + o];
}

__global__ __launch_bounds__(256) void fc_fused(
        const __nv_bfloat16* __restrict__ s3, const float* __restrict__ fw,
        const float* __restrict__ bfc, float* __restrict__ hb,
        const __nv_bfloat16* __restrict__ p1, const float* __restrict__ pw,
        const float* __restrict__ Plb, const int* __restrict__ dom,
        float* __restrict__ pf) {
    if (blockIdx.x < 64) fc_shared_body(blockIdx.x, s3, fw, bfc, hb);
    else                 fc_priv_body(blockIdx.x - 64, p1, pw, Plb, dom, pf);
}

// ---------------------------------------------------------------------------
// Per-sample task-routed heads.
// ---------------------------------------------------------------------------
__global__ void heads_k(const float* __restrict__ h, const float* __restrict__ p,
                        const int* __restrict__ tt,
                        const float* __restrict__ W1, const float* __restrict__ b1,
                        const float* __restrict__ W2, const float* __restrict__ b2,
                        const float* __restrict__ W3, const float* __restrict__ b3,
                        float* __restrict__ out) {
    int bi = blockIdx.x * blockDim.x + threadIdx.x;
    if (bi >= 1024) return;
    int t = tt[bi];
    float x[24];
    #pragma unroll
    for (int i = 0; i < 12; i++) { x[i] = h[bi * 12 + i]; x[12 + i] = p[bi * 12 + i]; }
    float h1[28];
    const float* w1 = W1 + t * 28 * 24;
    #pragma unroll
    for (int i = 0; i < 28; i++) {
        float s = b1[t * 28 + i];
        #pragma unroll
        for (int j = 0; j < 24; j++) s = fmaf(w1[i * 24 + j], x[j], s);
        h1[i] = fmaxf(s, 0.f);
    }
    float h2[14];
    const float* w2 = W2 + t * 14 * 28;
    #pragma unroll
    for (int i = 0; i < 14; i++) {
        float s = b2[t * 14 + i];
        #pragma unroll
        for (int j = 0; j < 28; j++) s = fmaf(w2[i * 28 + j], h1[j], s);
        h2[i] = fmaxf(s, 0.f);
    }
    const float* w3 = W3 + t * 5 * 14;
    #pragma unroll
    for (int i = 0; i < 5; i++) {
        float s = b3[t * 5 + i];
        #pragma unroll
        for (int j = 0; j < 14; j++) s = fmaf(w3[i * 14 + j], h2[j], s);
        out[bi * 5 + i] = s;
    }
}

// ---------------------------------------------------------------------------
// Launch
// ---------------------------------------------------------------------------
extern "C" void kernel_launch(void* const* d_in, const int* in_sizes, int n_in,
                              void* d_out, int out_size) {
    const float* x_s      = (const float*)d_in[0];
    const float* x_p      = (const float*)d_in[1];
    const int*   tt       = (const int*)  d_in[2];
    const int*   dom      = (const int*)  d_in[3];
    const float* Ws_in_W  = (const float*)d_in[4];
    const float* Ws_in_b  = (const float*)d_in[5];
    const float* Ws_hid_W = (const float*)d_in[6];
    const float* Ws_hid_b = (const float*)d_in[7];
    const float* Ws_fc_W  = (const float*)d_in[8];
    const float* Ws_fc_b  = (const float*)d_in[9];
    const float* Pc_W     = (const float*)d_in[10];
    const float* Pc_b     = (const float*)d_in[11];
    const float* Pl_W     = (const float*)d_in[12];
    const float* Pl_b     = (const float*)d_in[13];
    const float* H1W      = (const float*)d_in[14];
    const float* H1b      = (const float*)d_in[15];
    const float* H2W      = (const float*)d_in[16];
    const float* H2b      = (const float*)d_in[17];
    const float* H3W      = (const float*)d_in[18];
    const float* H3b      = (const float*)d_in[19];
    float* out = (float*)d_out;

    __nv_bfloat16 *s1, *s2, *s3, *p1;
    float *hb, *pf, *pw, *fw;
    uint32_t *bf1, *bfp, *bmid;
    cudaGetSymbolAddress((void**)&s1, g_s1);
    cudaGetSymbolAddress((void**)&s2, g_s2);
    cudaGetSymbolAddress((void**)&s3, g_s3);
    cudaGetSymbolAddress((void**)&hb, g_h);
    cudaGetSymbolAddress((void**)&p1, g_p1);
    cudaGetSymbolAddress((void**)&pf, g_pf);
    cudaGetSymbolAddress((void**)&pw, g_pw);
    cudaGetSymbolAddress((void**)&fw, g_fw);
    cudaGetSymbolAddress((void**)&bf1, g_bf1);
    cudaGetSymbolAddress((void**)&bfp, g_bfp);
    cudaGetSymbolAddress((void**)&bmid, g_bmid);

    const int SM_CF  = (66 * 144 + 960 + 40) * 4;            // 42016
    const int SM_S32 = (18 * 688 + 7680 + 40) * 4;           // 80416
    const int SM_M16 = (18 * 368 + 7680 + 40) * 4;           // 57376
    const int SM_FC  = 12 * 2304 * 4;                        // 110592

    cudaFuncSetAttribute((const void*)conv_first_fused,
                         cudaFuncAttributeMaxDynamicSharedMemorySize, SM_CF);
    cudaFuncSetAttribute((const void*)conv_mid32_k,
                         cudaFuncAttributeMaxDynamicSharedMemorySize, SM_S32);
    cudaFuncSetAttribute((const void*)conv_mid16_k,
                         cudaFuncAttributeMaxDynamicSharedMemorySize, SM_M16);
    cudaFuncSetAttribute((const void*)fc_fused,
                         cudaFuncAttributeMaxDynamicSharedMemorySize, SM_FC);

    prep_k<<<64, 256>>>(Ws_in_W, Pc_W, dom, Ws_hid_W, Pl_W, Ws_fc_W,
                        pw, fw, bf1, bfp, bmid);
    conv_first_fused<<<2048, 256, SM_CF>>>(x_s, bf1, Ws_in_b,
                                           x_p, bfp, Pc_b, dom,
                                           (uint32_t*)s1, (uint32_t*)p1);
    conv_mid32_k<<<2048, 256, SM_S32>>>(s1, Ws_hid_b, bmid, (uint32_t*)s2);
    conv_mid16_k<<<512, 256, SM_M16>>>(s2, Ws_hid_b, bmid, (uint32_t*)s3);
    fc_fused<<<128, 256, SM_FC>>>(s3, fw, Ws_fc_b, hb, p1, pw, Pl_b, dom, pf);
    heads_k<<<4, 256>>>(hb, pf, tt, H1W, H1b, H2W, H2b, H3W, H3b, out);
}